// round 4
// baseline (speedup 1.0000x reference)
/*
 * Swin-style window-attention block, fp32 SIMT baseline (R3).
 * Pipeline: LN1+window-partition -> qkv GEMM (scatter q/k/v head-major)
 * -> per-(window,head) attention CTA with rel-pos bias + softmax
 * -> proj GEMM (fused unpartition+residual) -> LN2 -> MLP1+GELU -> MLP2+residual.
 * Theory: GEMMs ~494 GFLOP fp32 vs ~36 TF/s FFMA ceiling => FMA-bound,
 * predicted 15-25 ms. Optimization target for later rounds: tcgen05 GEMMs.
 */
#include <cuda_runtime.h>
#include <math.h>

#define DIM   768
#define NHEAD 12
#define HDIM  64
#define WS    14
#define NTOK  196
#define NWIN  25
#define BATCH 8
#define NWB   200
#define TOKW  39200
#define TOKX  32768
#define BH    2400

__device__ float g_hwin[(size_t)TOKW * DIM];
__device__ float g_q[(size_t)BH * NTOK * HDIM];
__device__ float g_k[(size_t)BH * NTOK * HDIM];
__device__ float g_v[(size_t)BH * NTOK * HDIM];
__device__ float g_ao[(size_t)TOKW * DIM];
__device__ float g_x2[(size_t)TOKX * DIM];
__device__ float g_ln2[(size_t)TOKX * DIM];
__device__ float g_h1[(size_t)TOKX * 3072];

__global__ __launch_bounds__(256) void ln1_kernel(const float* __restrict__ x,
                                                  const float* __restrict__ g,
                                                  const float* __restrict__ b)
{
    int widx = blockIdx.x;
    int win = widx / NTOK, tok = widx - win * NTOK;
    int bb = win / NWIN, rem = win - bb * NWIN;
    int y = (rem / 5) * WS + tok / WS;
    int xx = (rem % 5) * WS + tok % WS;
    float* o = g_hwin + (size_t)widx * DIM;
    int tid = threadIdx.x;
    if (y >= 64 || xx >= 64) {
        for (int i = tid; i < DIM; i += 256) o[i] = 0.f;
        return;
    }
    const float* row = x + ((size_t)(bb * 64 + y) * 64 + xx) * DIM;
    float v0 = row[tid], v1 = row[tid + 256], v2 = row[tid + 512];
    float s = v0 + v1 + v2, sq = v0 * v0 + v1 * v1 + v2 * v2;
    #pragma unroll
    for (int off = 16; off; off >>= 1) {
        s  += __shfl_xor_sync(0xffffffffu, s, off);
        sq += __shfl_xor_sync(0xffffffffu, sq, off);
    }
    __shared__ float rs[8], rq[8], smu, srs;
    int wid = tid >> 5, lane = tid & 31;
    if (!lane) { rs[wid] = s; rq[wid] = sq; }
    __syncthreads();
    if (tid == 0) {
        float S = 0, Q = 0;
        #pragma unroll
        for (int i = 0; i < 8; i++) { S += rs[i]; Q += rq[i]; }
        float mu = S * (1.f / 768.f);
        float var = Q * (1.f / 768.f) - mu * mu;
        smu = mu; srs = rsqrtf(var + 1e-5f);
    }
    __syncthreads();
    float mu = smu, r = srs;
    o[tid]       = (v0 - mu) * r * g[tid]       + b[tid];
    o[tid + 256] = (v1 - mu) * r * g[tid + 256] + b[tid + 256];
    o[tid + 512] = (v2 - mu) * r * g[tid + 512] + b[tid + 512];
}

__global__ __launch_bounds__(256) void ln2_kernel(const float* __restrict__ g,
                                                  const float* __restrict__ b)
{
    int tid = threadIdx.x;
    const float* row = g_x2 + (size_t)blockIdx.x * DIM;
    float* o = g_ln2 + (size_t)blockIdx.x * DIM;
    float v0 = row[tid], v1 = row[tid + 256], v2 = row[tid + 512];
    float s = v0 + v1 + v2, sq = v0 * v0 + v1 * v1 + v2 * v2;
    #pragma unroll
    for (int off = 16; off; off >>= 1) {
        s  += __shfl_xor_sync(0xffffffffu, s, off);
        sq += __shfl_xor_sync(0xffffffffu, sq, off);
    }
    __shared__ float rs[8], rq[8], smu, srs;
    int wid = tid >> 5, lane = tid & 31;
    if (!lane) { rs[wid] = s; rq[wid] = sq; }
    __syncthreads();
    if (tid == 0) {
        float S = 0, Q = 0;
        #pragma unroll
        for (int i = 0; i < 8; i++) { S += rs[i]; Q += rq[i]; }
        float mu = S * (1.f / 768.f);
        float var = Q * (1.f / 768.f) - mu * mu;
        smu = mu; srs = rsqrtf(var + 1e-5f);
    }
    __syncthreads();
    float mu = smu, r = srs;
    o[tid]       = (v0 - mu) * r * g[tid]       + b[tid];
    o[tid + 256] = (v1 - mu) * r * g[tid + 256] + b[tid + 256];
    o[tid + 512] = (v2 - mu) * r * g[tid + 512] + b[tid + 512];
}

/*
 * SGEMM 128x128x16 tile, 256 threads, 8x8 accum per thread.
 * MODE 0: g_hwin[39200,768] x qkv_w[768,2304]  -> q(*0.125)/k/v head-major
 * MODE 1: g_ao[39200,768]   x proj_w[768,768]  -> g_x2 = x + unpartition(.)
 * MODE 2: g_ln2[32768,768]  x mlp_w1[768,3072] -> g_h1 = gelu(.)
 * MODE 3: g_h1[32768,3072]  x mlp_w2[3072,768] -> out = g_x2 + .
 */
template <int MODE>
__global__ __launch_bounds__(256) void gemm_kernel(const float* __restrict__ Bmat,
                                                   const float* __restrict__ bias,
                                                   const float* __restrict__ aux,
                                                   float* __restrict__ outp)
{
    constexpr int K  = (MODE == 3) ? 3072 : 768;
    constexpr int Nn = (MODE == 0) ? 2304 : (MODE == 2) ? 3072 : 768;
    constexpr int M  = (MODE <= 1) ? TOKW : TOKX;
    const float* A = (MODE == 0) ? g_hwin : (MODE == 1) ? g_ao : (MODE == 2) ? g_ln2 : g_h1;

    __shared__ float As[16 * 128];
    __shared__ float Bs[16 * 128];

    int tid = threadIdx.x;
    int n0 = blockIdx.x * 128, m0 = blockIdx.y * 128;
    int arow = tid >> 1, acol = (tid & 1) * 8;
    int brow = tid >> 4, bcol = (tid & 15) * 8;
    int tx = tid & 15, ty = tid >> 4;

    float acc[8][8];
    #pragma unroll
    for (int i = 0; i < 8; i++)
        #pragma unroll
        for (int j = 0; j < 8; j++) acc[i][j] = 0.f;

    const bool arow_ok = (m0 + arow) < M;
    const float* Aptr = A + (size_t)(m0 + arow) * K + acol;
    const float* Bptr = Bmat + (size_t)brow * Nn + n0 + bcol;

    for (int k0 = 0; k0 < K; k0 += 16) {
        float4 a0, a1;
        if (arow_ok) {
            a0 = *(const float4*)(Aptr + k0);
            a1 = *(const float4*)(Aptr + k0 + 4);
        } else {
            a0 = make_float4(0.f, 0.f, 0.f, 0.f); a1 = a0;
        }
        As[(acol + 0) * 128 + arow] = a0.x;
        As[(acol + 1) * 128 + arow] = a0.y;
        As[(acol + 2) * 128 + arow] = a0.z;
        As[(acol + 3) * 128 + arow] = a0.w;
        As[(acol + 4) * 128 + arow] = a1.x;
        As[(acol + 5) * 128 + arow] = a1.y;
        As[(acol + 6) * 128 + arow] = a1.z;
        As[(acol + 7) * 128 + arow] = a1.w;
        float4 b0 = *(const float4*)(Bptr + (size_t)k0 * Nn);
        float4 b1 = *(const float4*)(Bptr + (size_t)k0 * Nn + 4);
        *(float4*)&Bs[brow * 128 + bcol]     = b0;
        *(float4*)&Bs[brow * 128 + bcol + 4] = b1;
        __syncthreads();
        #pragma unroll
        for (int kk = 0; kk < 16; kk++) {
            float4 aA = *(const float4*)&As[kk * 128 + ty * 8];
            float4 aB = *(const float4*)&As[kk * 128 + ty * 8 + 4];
            float4 bA = *(const float4*)&Bs[kk * 128 + tx * 8];
            float4 bB = *(const float4*)&Bs[kk * 128 + tx * 8 + 4];
            float ar[8] = {aA.x, aA.y, aA.z, aA.w, aB.x, aB.y, aB.z, aB.w};
            float br[8] = {bA.x, bA.y, bA.z, bA.w, bB.x, bB.y, bB.z, bB.w};
            #pragma unroll
            for (int i = 0; i < 8; i++)
                #pragma unroll
                for (int j = 0; j < 8; j++) acc[i][j] += ar[i] * br[j];
        }
        __syncthreads();
    }

    #pragma unroll
    for (int i = 0; i < 8; i++) {
        int m = m0 + ty * 8 + i;
        if (m >= M) break;
        int win = 0, tok = 0;
        if (MODE <= 1) { win = m / NTOK; tok = m - win * NTOK; }
        #pragma unroll
        for (int j = 0; j < 8; j++) {
            int n = n0 + tx * 8 + j;
            float v = acc[i][j] + bias[n];
            if (MODE == 0) {
                int which = n / 768;
                int dd = n - which * 768;
                int head = dd >> 6, hd = dd & 63;
                size_t o = ((size_t)(win * NHEAD + head) * NTOK + tok) * HDIM + hd;
                if (which == 0)      g_q[o] = v * 0.125f;
                else if (which == 1) g_k[o] = v;
                else                 g_v[o] = v;
            } else if (MODE == 1) {
                int bb = win / NWIN, rem = win - bb * NWIN;
                int y  = (rem / 5) * WS + tok / WS;
                int xx = (rem % 5) * WS + tok % WS;
                if (y < 64 && xx < 64) {
                    size_t o = ((size_t)(bb * 64 + y) * 64 + xx) * DIM + n;
                    g_x2[o] = aux[o] + v;
                }
            } else if (MODE == 2) {
                g_h1[(size_t)m * 3072 + n] = 0.5f * v * (1.f + erff(v * 0.70710678118f));
            } else {
                outp[(size_t)m * DIM + n] = v + g_x2[(size_t)m * DIM + n];
            }
        }
    }
}

#define KV_STRIDE 68
#define SM_KS   0
#define SM_VS   (NTOK * KV_STRIDE)
#define SM_PROW (2 * NTOK * KV_STRIDE)
#define SM_QROW (SM_PROW + 4 * 200)
#define SM_SH   (SM_QROW + 4 * KV_STRIDE)
#define SM_SW   (SM_SH + NTOK)
#define SM_RSH  (SM_SW + NTOK)
#define SM_RSW  (SM_RSH + 32)
#define SM_FLOATS (SM_RSW + 32)
#define SM_BYTES_F (SM_FLOATS * 4)
#define SM_ATT_TOTAL (SM_BYTES_F + 4 * NTOK + 16)

__global__ __launch_bounds__(128) void attn_kernel(const float* __restrict__ rel_h,
                                                   const float* __restrict__ rel_w,
                                                   const int* __restrict__ q_idx,
                                                   const int* __restrict__ k_idx)
{
    extern __shared__ float sm[];
    float* ks   = sm + SM_KS;
    float* vs   = sm + SM_VS;
    float* prow = sm + SM_PROW;
    float* qrow = sm + SM_QROW;
    float* Sh   = sm + SM_SH;
    float* Sw   = sm + SM_SW;
    float* rsh  = sm + SM_RSH;
    float* rsw  = sm + SM_RSW;
    unsigned char* qr8 = (unsigned char*)(sm + SM_FLOATS);
    unsigned char* qc8 = qr8 + NTOK;
    unsigned char* kr8 = qc8 + NTOK;
    unsigned char* kc8 = kr8 + NTOK;

    int bh = blockIdx.x;
    int win = bh / NHEAD, head = bh - win * NHEAD;
    int tid = threadIdx.x;

    const float* kg = g_k + (size_t)bh * NTOK * HDIM;
    const float* vg = g_v + (size_t)bh * NTOK * HDIM;
    for (int i = tid; i < NTOK * HDIM; i += 128) {
        int j = i >> 6, d = i & 63;
        ks[j * KV_STRIDE + d] = kg[i];
        vs[j * KV_STRIDE + d] = vg[i];
    }
    if (tid < 27) {
        const float* rp = rel_h + tid * HDIM;
        float s = 0;
        #pragma unroll 8
        for (int c = 0; c < HDIM; c++) s += rp[c];
        rsh[tid] = s;
    } else if (tid >= 32 && tid < 59) {
        const float* rp = rel_w + (tid - 32) * HDIM;
        float s = 0;
        #pragma unroll 8
        for (int c = 0; c < HDIM; c++) s += rp[c];
        rsw[tid - 32] = s;
    }
    for (int t = tid; t < NTOK; t += 128) {
        int qi = q_idx[(size_t)bh * NTOK + t];
        int ki = k_idx[(size_t)bh * NTOK + t];
        qr8[t] = (unsigned char)(qi / WS);
        qc8[t] = (unsigned char)(qi % WS);
        kr8[t] = (unsigned char)(ki / WS);
        kc8[t] = (unsigned char)(ki % WS);
    }
    __syncthreads();
    for (int t = tid; t < NTOK; t += 128) {
        int i = t / WS, j = t - i * WS;
        Sh[t] = rsh[i - j + WS - 1];
        Sw[t] = rsw[i - j + WS - 1];
    }
    __syncthreads();

    int w = tid >> 5, lane = tid & 31;
    float* qw = qrow + w * KV_STRIDE;
    float* pw = prow + w * 200;
    const float* qg = g_q + (size_t)bh * NTOK * HDIM;

    for (int row = w; row < NTOK; row += 4) {
        qw[lane]      = qg[row * HDIM + lane];
        qw[lane + 32] = qg[row * HDIM + 32 + lane];
        __syncwarp();
        int qrr = qr8[row] * WS, qcc = qc8[row] * WS;
        float s[7];
        #pragma unroll
        for (int jj = 0; jj < 7; jj++) {
            int j = lane + jj * 32;
            if (j < NTOK) {
                const float4* kk = (const float4*)(ks + j * KV_STRIDE);
                float acc = 0;
                #pragma unroll
                for (int d4 = 0; d4 < 16; d4++) {
                    float4 kv = kk[d4];
                    float4 qv = *(const float4*)(qw + d4 * 4);
                    acc += kv.x * qv.x + kv.y * qv.y + kv.z * qv.z + kv.w * qv.w;
                }
                s[jj] = acc + Sh[qrr + kr8[j]] + Sw[qcc + kc8[j]];
            } else {
                s[jj] = -1e30f;
            }
        }
        float mx = s[0];
        #pragma unroll
        for (int jj = 1; jj < 7; jj++) mx = fmaxf(mx, s[jj]);
        #pragma unroll
        for (int off = 16; off; off >>= 1) mx = fmaxf(mx, __shfl_xor_sync(0xffffffffu, mx, off));
        float sum = 0;
        #pragma unroll
        for (int jj = 0; jj < 7; jj++) {
            int j = lane + jj * 32;
            float e = (j < NTOK) ? expf(s[jj] - mx) : 0.f;
            s[jj] = e;
            sum += e;
        }
        #pragma unroll
        for (int off = 16; off; off >>= 1) sum += __shfl_xor_sync(0xffffffffu, sum, off);
        float inv = 1.f / sum;
        #pragma unroll
        for (int jj = 0; jj < 7; jj++) {
            int j = lane + jj * 32;
            if (j < 200) pw[j] = s[jj];
        }
        __syncwarp();
        int d = 2 * lane;
        float o0 = 0, o1 = 0;
        #pragma unroll 7
        for (int j = 0; j < NTOK; j += 4) {
            float4 p4 = *(const float4*)(pw + j);
            const float* vb = vs + j * KV_STRIDE + d;
            float2 va  = *(const float2*)(vb);
            float2 vb1 = *(const float2*)(vb + KV_STRIDE);
            float2 vc  = *(const float2*)(vb + 2 * KV_STRIDE);
            float2 vd_ = *(const float2*)(vb + 3 * KV_STRIDE);
            o0 += p4.x * va.x + p4.y * vb1.x + p4.z * vc.x + p4.w * vd_.x;
            o1 += p4.x * va.y + p4.y * vb1.y + p4.z * vc.y + p4.w * vd_.y;
        }
        float* og = g_ao + ((size_t)(win * NTOK + row)) * DIM + head * HDIM;
        og[d]     = o0 * inv;
        og[d + 1] = o1 * inv;
        __syncwarp();
    }
}

extern "C" void kernel_launch(void* const* d_in, const int* in_sizes, int n_in,
                              void* d_out, int out_size)
{
    const float* x     = (const float*)d_in[0];
    const int*   qidx  = (const int*)d_in[1];
    const int*   kidx  = (const int*)d_in[2];
    const float* ln1w  = (const float*)d_in[3];
    const float* ln1b  = (const float*)d_in[4];
    const float* ln2w  = (const float*)d_in[5];
    const float* ln2b  = (const float*)d_in[6];
    const float* qkvw  = (const float*)d_in[7];
    const float* qkvb  = (const float*)d_in[8];
    const float* projw = (const float*)d_in[9];
    const float* projb = (const float*)d_in[10];
    const float* relh  = (const float*)d_in[11];
    const float* relw  = (const float*)d_in[12];
    const float* w1    = (const float*)d_in[13];
    const float* b1    = (const float*)d_in[14];
    const float* w2    = (const float*)d_in[15];
    const float* b2    = (const float*)d_in[16];
    float* out = (float*)d_out;

    static bool attr_set = false;
    if (!attr_set) {
        cudaFuncSetAttribute(attn_kernel, cudaFuncAttributeMaxDynamicSharedMemorySize, SM_ATT_TOTAL);
        attr_set = true;
    }

    ln1_kernel<<<TOKW, 256>>>(x, ln1w, ln1b);
    gemm_kernel<0><<<dim3(2304 / 128, (TOKW + 127) / 128), 256>>>(qkvw, qkvb, nullptr, nullptr);
    attn_kernel<<<BH, 128, SM_ATT_TOTAL>>>(relh, relw, qidx, kidx);
    gemm_kernel<1><<<dim3(768 / 128, (TOKW + 127) / 128), 256>>>(projw, projb, x, nullptr);
    ln2_kernel<<<TOKX, 256>>>(ln2w, ln2b);
    gemm_kernel<2><<<dim3(3072 / 128, TOKX / 128), 256>>>(w1, b1, nullptr, nullptr);
    gemm_kernel<3><<<dim3(768 / 128, TOKX / 128), 256>>>(w2, b2, nullptr, out);
}

// round 6
// speedup vs baseline: 2.0123x; 2.0123x over previous
/*
 * R6: mma.sync (HMMA) bf16x3 compensated GEMMs + cp.async pipeline.
 * tcgen05 rejected: harness builds PTX at compute_103 (no 'a' features).
 */
#include <cuda_runtime.h>
#include <cuda_bf16.h>
#include <math.h>
#include <stdint.h>

#define DIM   768
#define NHEAD 12
#define HDIM  64
#define WS    14
#define NTOK  196
#define NWIN  25
#define BATCH 8
#define NWB   200
#define TOKW  39200
#define TOKW_PAD 39296
#define TOKX  32768
#define BH    2400

// ---------------- device scratch ----------------
__device__ __nv_bfloat16 g_a_h[(size_t)TOKW_PAD * DIM];
__device__ __nv_bfloat16 g_a_l[(size_t)TOKW_PAD * DIM];
__device__ __nv_bfloat16 g_ao_h[(size_t)TOKW_PAD * DIM];
__device__ __nv_bfloat16 g_ao_l[(size_t)TOKW_PAD * DIM];
__device__ __nv_bfloat16 g_b_h[(size_t)TOKX * DIM];
__device__ __nv_bfloat16 g_b_l[(size_t)TOKX * DIM];
__device__ __nv_bfloat16 g_h1_h[(size_t)TOKX * 3072];
__device__ __nv_bfloat16 g_h1_l[(size_t)TOKX * 3072];
__device__ __nv_bfloat16 g_wqkv_h[(size_t)2304 * 768];
__device__ __nv_bfloat16 g_wqkv_l[(size_t)2304 * 768];
__device__ __nv_bfloat16 g_wproj_h[(size_t)768 * 768];
__device__ __nv_bfloat16 g_wproj_l[(size_t)768 * 768];
__device__ __nv_bfloat16 g_w1_h[(size_t)3072 * 768];
__device__ __nv_bfloat16 g_w1_l[(size_t)3072 * 768];
__device__ __nv_bfloat16 g_w2_h[(size_t)768 * 3072];
__device__ __nv_bfloat16 g_w2_l[(size_t)768 * 3072];
__device__ float g_q[(size_t)BH * NTOK * HDIM];
__device__ float g_k[(size_t)BH * NTOK * HDIM];
__device__ float g_v[(size_t)BH * NTOK * HDIM];
__device__ float g_x2[(size_t)TOKX * DIM];

// ---------------- PTX helpers (all baseline sm_80-class) ----------------
__device__ __forceinline__ uint32_t smem_u32(const void* p) {
    uint32_t a;
    asm("{ .reg .u64 t; cvta.to.shared.u64 t, %1; cvt.u32.u64 %0, t; }" : "=r"(a) : "l"(p));
    return a;
}
__device__ __forceinline__ void cp16(uint32_t dst, const void* src) {
    asm volatile("cp.async.cg.shared.global [%0], [%1], 16;" :: "r"(dst), "l"(src));
}
__device__ __forceinline__ void ldsm_x4(uint32_t* r, uint32_t addr) {
    asm volatile("ldmatrix.sync.aligned.m8n8.x4.shared.b16 {%0,%1,%2,%3}, [%4];"
        : "=r"(r[0]), "=r"(r[1]), "=r"(r[2]), "=r"(r[3]) : "r"(addr));
}
__device__ __forceinline__ void ldsm_x2(uint32_t* r, uint32_t addr) {
    asm volatile("ldmatrix.sync.aligned.m8n8.x2.shared.b16 {%0,%1}, [%2];"
        : "=r"(r[0]), "=r"(r[1]) : "r"(addr));
}
__device__ __forceinline__ void mma_bf16(float* c, const uint32_t* a, const uint32_t* b) {
    asm volatile(
        "mma.sync.aligned.m16n8k16.row.col.f32.bf16.bf16.f32 "
        "{%0,%1,%2,%3}, {%4,%5,%6,%7}, {%8,%9}, {%0,%1,%2,%3};"
        : "+f"(c[0]), "+f"(c[1]), "+f"(c[2]), "+f"(c[3])
        : "r"(a[0]), "r"(a[1]), "r"(a[2]), "r"(a[3]), "r"(b[0]), "r"(b[1]));
}
__device__ __forceinline__ void bf16split(float v, __nv_bfloat16& h, __nv_bfloat16& l) {
    h = __float2bfloat16(v);
    l = __float2bfloat16(v - __bfloat162float(h));
}

// ---------------- weight transpose + bf16 split: W[K,N] -> Wt_h/l[N,K] ----------------
__global__ __launch_bounds__(256) void wsplit_kernel(const float* __restrict__ W,
                                                     __nv_bfloat16* __restrict__ Wh,
                                                     __nv_bfloat16* __restrict__ Wl,
                                                     int K, int N)
{
    __shared__ float tile[32][33];
    int k0 = blockIdx.y * 32, n0 = blockIdx.x * 32;
    int tx = threadIdx.x & 31, ty = threadIdx.x >> 5;
    #pragma unroll
    for (int j = 0; j < 32; j += 8)
        tile[ty + j][tx] = W[(size_t)(k0 + ty + j) * N + n0 + tx];
    __syncthreads();
    #pragma unroll
    for (int j = 0; j < 32; j += 8) {
        float v = tile[tx][ty + j];
        __nv_bfloat16 h, l;
        bf16split(v, h, l);
        size_t o = (size_t)(n0 + ty + j) * K + k0 + tx;
        Wh[o] = h; Wl[o] = l;
    }
}

// ---------------- LayerNorm 1 (fused window partition + pad + bf16 split) ----------------
__global__ __launch_bounds__(256) void ln1_kernel(const float* __restrict__ x,
                                                  const float* __restrict__ g,
                                                  const float* __restrict__ b)
{
    int widx = blockIdx.x;
    int win = widx / NTOK, tok = widx - win * NTOK;
    int bb = win / NWIN, rem = win - bb * NWIN;
    int y = (rem / 5) * WS + tok / WS;
    int xx = (rem % 5) * WS + tok % WS;
    size_t ob = (size_t)widx * DIM;
    int tid = threadIdx.x;
    if (y >= 64 || xx >= 64) {
        for (int i = tid; i < DIM; i += 256) {
            g_a_h[ob + i] = __float2bfloat16(0.f);
            g_a_l[ob + i] = __float2bfloat16(0.f);
        }
        return;
    }
    const float* row = x + ((size_t)(bb * 64 + y) * 64 + xx) * DIM;
    float v0 = row[tid], v1 = row[tid + 256], v2 = row[tid + 512];
    float s = v0 + v1 + v2, sq = v0 * v0 + v1 * v1 + v2 * v2;
    #pragma unroll
    for (int off = 16; off; off >>= 1) {
        s  += __shfl_xor_sync(0xffffffffu, s, off);
        sq += __shfl_xor_sync(0xffffffffu, sq, off);
    }
    __shared__ float rs[8], rq[8], smu, srs;
    int wid = tid >> 5, lane = tid & 31;
    if (!lane) { rs[wid] = s; rq[wid] = sq; }
    __syncthreads();
    if (tid == 0) {
        float S = 0, Q = 0;
        #pragma unroll
        for (int i = 0; i < 8; i++) { S += rs[i]; Q += rq[i]; }
        float mu = S * (1.f / 768.f);
        float var = Q * (1.f / 768.f) - mu * mu;
        smu = mu; srs = rsqrtf(var + 1e-5f);
    }
    __syncthreads();
    float mu = smu, r = srs;
    #pragma unroll
    for (int p = 0; p < 3; p++) {
        int i = tid + p * 256;
        float vv = ((p == 0 ? v0 : p == 1 ? v1 : v2) - mu) * r * g[i] + b[i];
        __nv_bfloat16 h, l;
        bf16split(vv, h, l);
        g_a_h[ob + i] = h; g_a_l[ob + i] = l;
    }
}

// ---------------- LayerNorm 2 (bf16 split out) ----------------
__global__ __launch_bounds__(256) void ln2_kernel(const float* __restrict__ g,
                                                  const float* __restrict__ b)
{
    int tid = threadIdx.x;
    const float* row = g_x2 + (size_t)blockIdx.x * DIM;
    size_t ob = (size_t)blockIdx.x * DIM;
    float v0 = row[tid], v1 = row[tid + 256], v2 = row[tid + 512];
    float s = v0 + v1 + v2, sq = v0 * v0 + v1 * v1 + v2 * v2;
    #pragma unroll
    for (int off = 16; off; off >>= 1) {
        s  += __shfl_xor_sync(0xffffffffu, s, off);
        sq += __shfl_xor_sync(0xffffffffu, sq, off);
    }
    __shared__ float rs[8], rq[8], smu, srs;
    int wid = tid >> 5, lane = tid & 31;
    if (!lane) { rs[wid] = s; rq[wid] = sq; }
    __syncthreads();
    if (tid == 0) {
        float S = 0, Q = 0;
        #pragma unroll
        for (int i = 0; i < 8; i++) { S += rs[i]; Q += rq[i]; }
        float mu = S * (1.f / 768.f);
        float var = Q * (1.f / 768.f) - mu * mu;
        smu = mu; srs = rsqrtf(var + 1e-5f);
    }
    __syncthreads();
    float mu = smu, r = srs;
    #pragma unroll
    for (int p = 0; p < 3; p++) {
        int i = tid + p * 256;
        float vv = ((p == 0 ? v0 : p == 1 ? v1 : v2) - mu) * r * g[i] + b[i];
        __nv_bfloat16 h, l;
        bf16split(vv, h, l);
        g_b_h[ob + i] = h; g_b_l[ob + i] = l;
    }
}

// ---------------- mma.sync GEMM: D[M,N] = A[M,K] x Wt[N,K]^T, bf16x3 ----------------
// CTA 128x128, 8 warps (2x4), warp tile 64x32, K-chunk 32, cp.async double buffer.
// Smem per stage: Ah,Al,Bh,Bl each 128 rows x 40 bf16 (80B stride) = 10240B.
#define TG_STAGE_B  40960
#define TG_MAT_B    10240
#define SMEM_TG     (2 * TG_STAGE_B)

template <int MODE>
__global__ __launch_bounds__(256) void tgemm_kernel(const float* __restrict__ bias,
                                                    const float* __restrict__ aux,
                                                    float* __restrict__ outp)
{
    constexpr int K      = (MODE == 3) ? 3072 : 768;
    constexpr int Mreal  = (MODE <= 1) ? TOKW : TOKX;
    constexpr int NCHUNK = K / 32;
    const __nv_bfloat16* gAh = (MODE == 0) ? g_a_h : (MODE == 1) ? g_ao_h : (MODE == 2) ? g_b_h : g_h1_h;
    const __nv_bfloat16* gAl = (MODE == 0) ? g_a_l : (MODE == 1) ? g_ao_l : (MODE == 2) ? g_b_l : g_h1_l;
    const __nv_bfloat16* gBh = (MODE == 0) ? g_wqkv_h : (MODE == 1) ? g_wproj_h : (MODE == 2) ? g_w1_h : g_w2_h;
    const __nv_bfloat16* gBl = (MODE == 0) ? g_wqkv_l : (MODE == 1) ? g_wproj_l : (MODE == 2) ? g_w1_l : g_w2_l;

    extern __shared__ char smem_raw[];
    const uint32_t sbase = smem_u32(smem_raw);

    const int t = threadIdx.x;
    const int m0 = blockIdx.y * 128;
    const int n0 = blockIdx.x * 128;
    const int warp = t >> 5, lane = t & 31;
    const int wm = warp >> 2, wn = warp & 3;

    float acc[4][4][4];
    #pragma unroll
    for (int a = 0; a < 4; a++)
        #pragma unroll
        for (int b2 = 0; b2 < 4; b2++)
            #pragma unroll
            for (int c = 0; c < 4; c++) acc[a][b2][c] = 0.f;

    const int ldrow = t >> 2, ldseg = t & 3;   // 64 rows per pass x 4 segs
    const uint32_t sm_off0 = (uint32_t)(ldrow * 80 + ldseg * 16);
    const uint32_t sm_off1 = (uint32_t)((ldrow + 64) * 80 + ldseg * 16);

    // ---- prefetch chunk 0 ----
    {
        const int k0 = 0;
        const uint32_t so = sbase;
        size_t ga0 = (size_t)(m0 + ldrow) * K + k0 + ldseg * 8;
        size_t ga1 = (size_t)(m0 + ldrow + 64) * K + k0 + ldseg * 8;
        size_t gb0 = (size_t)(n0 + ldrow) * K + k0 + ldseg * 8;
        size_t gb1 = (size_t)(n0 + ldrow + 64) * K + k0 + ldseg * 8;
        cp16(so + 0 * TG_MAT_B + sm_off0, gAh + ga0);
        cp16(so + 0 * TG_MAT_B + sm_off1, gAh + ga1);
        cp16(so + 1 * TG_MAT_B + sm_off0, gAl + ga0);
        cp16(so + 1 * TG_MAT_B + sm_off1, gAl + ga1);
        cp16(so + 2 * TG_MAT_B + sm_off0, gBh + gb0);
        cp16(so + 2 * TG_MAT_B + sm_off1, gBh + gb1);
        cp16(so + 3 * TG_MAT_B + sm_off0, gBl + gb0);
        cp16(so + 3 * TG_MAT_B + sm_off1, gBl + gb1);
        asm volatile("cp.async.commit_group;" ::: "memory");
    }

    // per-warp ldmatrix address pieces
    const int a_row_in = (lane & 7) + (lane & 8);       // 0..15
    const int a_koff   = (lane >> 4) * 8;               // 0 or 8
    const int b_row_in = lane & 7;
    const int b_koff   = ((lane >> 3) & 1) * 8;

    for (int i = 0; i < NCHUNK; i++) {
        const int s = i & 1;
        if (i + 1 < NCHUNK) {
            const int k0 = (i + 1) * 32;
            const uint32_t so = sbase + (uint32_t)((s ^ 1) * TG_STAGE_B);
            size_t ga0 = (size_t)(m0 + ldrow) * K + k0 + ldseg * 8;
            size_t ga1 = (size_t)(m0 + ldrow + 64) * K + k0 + ldseg * 8;
            size_t gb0 = (size_t)(n0 + ldrow) * K + k0 + ldseg * 8;
            size_t gb1 = (size_t)(n0 + ldrow + 64) * K + k0 + ldseg * 8;
            cp16(so + 0 * TG_MAT_B + sm_off0, gAh + ga0);
            cp16(so + 0 * TG_MAT_B + sm_off1, gAh + ga1);
            cp16(so + 1 * TG_MAT_B + sm_off0, gAl + ga0);
            cp16(so + 1 * TG_MAT_B + sm_off1, gAl + ga1);
            cp16(so + 2 * TG_MAT_B + sm_off0, gBh + gb0);
            cp16(so + 2 * TG_MAT_B + sm_off1, gBh + gb1);
            cp16(so + 3 * TG_MAT_B + sm_off0, gBl + gb0);
            cp16(so + 3 * TG_MAT_B + sm_off1, gBl + gb1);
            asm volatile("cp.async.commit_group;" ::: "memory");
            asm volatile("cp.async.wait_group 1;" ::: "memory");
        } else {
            asm volatile("cp.async.wait_group 0;" ::: "memory");
        }
        __syncthreads();

        const uint32_t soA = sbase + (uint32_t)(s * TG_STAGE_B);
        const uint32_t soB = soA + 2 * TG_MAT_B;
        #pragma unroll
        for (int ks = 0; ks < 2; ks++) {
            uint32_t ah[4][4], al[4][4], bh[4][2], bl[4][2];
            #pragma unroll
            for (int mt = 0; mt < 4; mt++) {
                int mr = wm * 64 + mt * 16 + a_row_in;
                uint32_t ad = soA + (uint32_t)((mr * 40 + ks * 16 + a_koff) * 2);
                ldsm_x4(ah[mt], ad);
                ldsm_x4(al[mt], ad + TG_MAT_B);
            }
            #pragma unroll
            for (int nt = 0; nt < 4; nt++) {
                int nr = wn * 32 + nt * 8 + b_row_in;
                uint32_t bd = soB + (uint32_t)((nr * 40 + ks * 16 + b_koff) * 2);
                ldsm_x2(bh[nt], bd);
                ldsm_x2(bl[nt], bd + TG_MAT_B);
            }
            #pragma unroll
            for (int mt = 0; mt < 4; mt++)
                #pragma unroll
                for (int nt = 0; nt < 4; nt++) {
                    mma_bf16(acc[mt][nt], ah[mt], bh[nt]);
                    mma_bf16(acc[mt][nt], al[mt], bh[nt]);
                    mma_bf16(acc[mt][nt], ah[mt], bl[nt]);
                }
        }
        __syncthreads();
    }

    // ---- epilogue ----
    const int g = lane >> 2, tq = lane & 3;
    #pragma unroll
    for (int mt = 0; mt < 4; mt++) {
        #pragma unroll
        for (int half = 0; half < 2; half++) {
            int m = m0 + wm * 64 + mt * 16 + g + half * 8;
            bool valid = (m < Mreal);
            int win = 0, tok = 0, yy = 0, xx = 0, bb = 0;
            if (MODE <= 1) {
                win = m / NTOK; tok = m - win * NTOK;
                if (MODE == 1) {
                    bb = win / NWIN; int rem = win - bb * NWIN;
                    yy = (rem / 5) * WS + tok / WS;
                    xx = (rem % 5) * WS + tok % WS;
                    valid = valid && (yy < 64) && (xx < 64);
                }
            }
            if (!valid) continue;
            #pragma unroll
            for (int nt = 0; nt < 4; nt++) {
                int n = n0 + wn * 32 + nt * 8 + 2 * tq;
                float v0 = acc[mt][nt][half * 2]     + bias[n];
                float v1 = acc[mt][nt][half * 2 + 1] + bias[n + 1];
                if (MODE == 0) {
                    int which = n / 768;
                    int dd = n - which * 768;
                    int head = dd >> 6, hd = dd & 63;
                    size_t o = ((size_t)(win * NHEAD + head) * NTOK + tok) * HDIM + hd;
                    if (which == 0)      { g_q[o] = v0 * 0.125f; g_q[o + 1] = v1 * 0.125f; }
                    else if (which == 1) { g_k[o] = v0; g_k[o + 1] = v1; }
                    else                 { g_v[o] = v0; g_v[o + 1] = v1; }
                } else if (MODE == 1) {
                    size_t o = ((size_t)(bb * 64 + yy) * 64 + xx) * DIM + n;
                    g_x2[o]     = aux[o] + v0;
                    g_x2[o + 1] = aux[o + 1] + v1;
                } else if (MODE == 2) {
                    float gl0 = 0.5f * v0 * (1.f + erff(v0 * 0.70710678118f));
                    float gl1 = 0.5f * v1 * (1.f + erff(v1 * 0.70710678118f));
                    __nv_bfloat16 h0, l0, h1, l1;
                    bf16split(gl0, h0, l0);
                    bf16split(gl1, h1, l1);
                    size_t o = (size_t)m * 3072 + n;
                    g_h1_h[o] = h0; g_h1_h[o + 1] = h1;
                    g_h1_l[o] = l0; g_h1_l[o + 1] = l1;
                } else {
                    size_t o = (size_t)m * DIM + n;
                    outp[o]     = v0 + g_x2[o];
                    outp[o + 1] = v1 + g_x2[o + 1];
                }
            }
        }
    }
}

// ---------------- attention: one CTA per (window, head), fp32 SIMT ----------------
#define KV_STRIDE 68
#define SM_KS   0
#define SM_VS   (NTOK * KV_STRIDE)
#define SM_PROW (2 * NTOK * KV_STRIDE)
#define SM_QROW (SM_PROW + 4 * 200)
#define SM_SH   (SM_QROW + 4 * KV_STRIDE)
#define SM_SW   (SM_SH + NTOK)
#define SM_RSH  (SM_SW + NTOK)
#define SM_RSW  (SM_RSH + 32)
#define SM_FLOATS (SM_RSW + 32)
#define SM_BYTES_F (SM_FLOATS * 4)
#define SM_ATT_TOTAL (SM_BYTES_F + 4 * NTOK + 16)

__global__ __launch_bounds__(128) void attn_kernel(const float* __restrict__ rel_h,
                                                   const float* __restrict__ rel_w,
                                                   const int* __restrict__ q_idx,
                                                   const int* __restrict__ k_idx)
{
    extern __shared__ float sm[];
    float* ks   = sm + SM_KS;
    float* vs   = sm + SM_VS;
    float* prow = sm + SM_PROW;
    float* qrow = sm + SM_QROW;
    float* Sh   = sm + SM_SH;
    float* Sw   = sm + SM_SW;
    float* rsh  = sm + SM_RSH;
    float* rsw  = sm + SM_RSW;
    unsigned char* qr8 = (unsigned char*)(sm + SM_FLOATS);
    unsigned char* qc8 = qr8 + NTOK;
    unsigned char* kr8 = qc8 + NTOK;
    unsigned char* kc8 = kr8 + NTOK;

    int bh = blockIdx.x;
    int win = bh / NHEAD, head = bh - win * NHEAD;
    int tid = threadIdx.x;

    const float* kg = g_k + (size_t)bh * NTOK * HDIM;
    const float* vg = g_v + (size_t)bh * NTOK * HDIM;
    for (int i = tid; i < NTOK * HDIM; i += 128) {
        int j = i >> 6, d = i & 63;
        ks[j * KV_STRIDE + d] = kg[i];
        vs[j * KV_STRIDE + d] = vg[i];
    }
    if (tid < 27) {
        const float* rp = rel_h + tid * HDIM;
        float s = 0;
        #pragma unroll 8
        for (int c = 0; c < HDIM; c++) s += rp[c];
        rsh[tid] = s;
    } else if (tid >= 32 && tid < 59) {
        const float* rp = rel_w + (tid - 32) * HDIM;
        float s = 0;
        #pragma unroll 8
        for (int c = 0; c < HDIM; c++) s += rp[c];
        rsw[tid - 32] = s;
    }
    for (int tt = tid; tt < NTOK; tt += 128) {
        int qi = q_idx[(size_t)bh * NTOK + tt];
        int ki = k_idx[(size_t)bh * NTOK + tt];
        qr8[tt] = (unsigned char)(qi / WS);
        qc8[tt] = (unsigned char)(qi % WS);
        kr8[tt] = (unsigned char)(ki / WS);
        kc8[tt] = (unsigned char)(ki % WS);
    }
    __syncthreads();
    for (int tt = tid; tt < NTOK; tt += 128) {
        int i = tt / WS, j = tt - i * WS;
        Sh[tt] = rsh[i - j + WS - 1];
        Sw[tt] = rsw[i - j + WS - 1];
    }
    __syncthreads();

    int w = tid >> 5, lane = tid & 31;
    float* qw = qrow + w * KV_STRIDE;
    float* pw = prow + w * 200;
    const float* qg = g_q + (size_t)bh * NTOK * HDIM;

    for (int row = w; row < NTOK; row += 4) {
        qw[lane]      = qg[row * HDIM + lane];
        qw[lane + 32] = qg[row * HDIM + 32 + lane];
        __syncwarp();
        int qrr = qr8[row] * WS, qcc = qc8[row] * WS;
        float s[7];
        #pragma unroll
        for (int jj = 0; jj < 7; jj++) {
            int j = lane + jj * 32;
            if (j < NTOK) {
                const float4* kk = (const float4*)(ks + j * KV_STRIDE);
                float acc = 0;
                #pragma unroll
                for (int d4 = 0; d4 < 16; d4++) {
                    float4 kv = kk[d4];
                    float4 qv = *(const float4*)(qw + d4 * 4);
                    acc += kv.x * qv.x + kv.y * qv.y + kv.z * qv.z + kv.w * qv.w;
                }
                s[jj] = acc + Sh[qrr + kr8[j]] + Sw[qcc + kc8[j]];
            } else {
                s[jj] = -1e30f;
            }
        }
        float mx = s[0];
        #pragma unroll
        for (int jj = 1; jj < 7; jj++) mx = fmaxf(mx, s[jj]);
        #pragma unroll
        for (int off = 16; off; off >>= 1) mx = fmaxf(mx, __shfl_xor_sync(0xffffffffu, mx, off));
        float sum = 0;
        #pragma unroll
        for (int jj = 0; jj < 7; jj++) {
            int j = lane + jj * 32;
            float e = (j < NTOK) ? expf(s[jj] - mx) : 0.f;
            s[jj] = e;
            sum += e;
        }
        #pragma unroll
        for (int off = 16; off; off >>= 1) sum += __shfl_xor_sync(0xffffffffu, sum, off);
        float inv = 1.f / sum;
        #pragma unroll
        for (int jj = 0; jj < 7; jj++) {
            int j = lane + jj * 32;
            if (j < 200) pw[j] = s[jj];
        }
        __syncwarp();
        int d = 2 * lane;
        float o0 = 0, o1 = 0;
        #pragma unroll 7
        for (int j = 0; j < NTOK; j += 4) {
            float4 p4 = *(const float4*)(pw + j);
            const float* vb = vs + j * KV_STRIDE + d;
            float2 va  = *(const float2*)(vb);
            float2 vb1 = *(const float2*)(vb + KV_STRIDE);
            float2 vc  = *(const float2*)(vb + 2 * KV_STRIDE);
            float2 vd_ = *(const float2*)(vb + 3 * KV_STRIDE);
            o0 += p4.x * va.x + p4.y * vb1.x + p4.z * vc.x + p4.w * vd_.x;
            o1 += p4.x * va.y + p4.y * vb1.y + p4.z * vc.y + p4.w * vd_.y;
        }
        size_t og = ((size_t)(win * NTOK + row)) * DIM + head * HDIM;
        float r0 = o0 * inv, r1 = o1 * inv;
        __nv_bfloat16 h0, l0, h1, l1;
        bf16split(r0, h0, l0);
        bf16split(r1, h1, l1);
        g_ao_h[og + d] = h0; g_ao_l[og + d] = l0;
        g_ao_h[og + d + 1] = h1; g_ao_l[og + d + 1] = l1;
        __syncwarp();
    }
}

// ---------------- launch ----------------
extern "C" void kernel_launch(void* const* d_in, const int* in_sizes, int n_in,
                              void* d_out, int out_size)
{
    const float* x     = (const float*)d_in[0];
    const int*   qidx  = (const int*)d_in[1];
    const int*   kidx  = (const int*)d_in[2];
    const float* ln1w  = (const float*)d_in[3];
    const float* ln1b  = (const float*)d_in[4];
    const float* ln2w  = (const float*)d_in[5];
    const float* ln2b  = (const float*)d_in[6];
    const float* qkvw  = (const float*)d_in[7];
    const float* qkvb  = (const float*)d_in[8];
    const float* projw = (const float*)d_in[9];
    const float* projb = (const float*)d_in[10];
    const float* relh  = (const float*)d_in[11];
    const float* relw  = (const float*)d_in[12];
    const float* w1    = (const float*)d_in[13];
    const float* b1    = (const float*)d_in[14];
    const float* w2    = (const float*)d_in[15];
    const float* b2    = (const float*)d_in[16];
    float* out = (float*)d_out;

    cudaFuncSetAttribute(attn_kernel, cudaFuncAttributeMaxDynamicSharedMemorySize, SM_ATT_TOTAL);
    cudaFuncSetAttribute(tgemm_kernel<0>, cudaFuncAttributeMaxDynamicSharedMemorySize, SMEM_TG);
    cudaFuncSetAttribute(tgemm_kernel<1>, cudaFuncAttributeMaxDynamicSharedMemorySize, SMEM_TG);
    cudaFuncSetAttribute(tgemm_kernel<2>, cudaFuncAttributeMaxDynamicSharedMemorySize, SMEM_TG);
    cudaFuncSetAttribute(tgemm_kernel<3>, cudaFuncAttributeMaxDynamicSharedMemorySize, SMEM_TG);

    __nv_bfloat16 *wqkv_h, *wqkv_l, *wproj_h, *wproj_l, *w1_h, *w1_l, *w2_h, *w2_l;
    cudaGetSymbolAddress((void**)&wqkv_h, g_wqkv_h);
    cudaGetSymbolAddress((void**)&wqkv_l, g_wqkv_l);
    cudaGetSymbolAddress((void**)&wproj_h, g_wproj_h);
    cudaGetSymbolAddress((void**)&wproj_l, g_wproj_l);
    cudaGetSymbolAddress((void**)&w1_h, g_w1_h);
    cudaGetSymbolAddress((void**)&w1_l, g_w1_l);
    cudaGetSymbolAddress((void**)&w2_h, g_w2_h);
    cudaGetSymbolAddress((void**)&w2_l, g_w2_l);

    wsplit_kernel<<<dim3(2304 / 32, 768 / 32), 256>>>(qkvw, wqkv_h, wqkv_l, 768, 2304);
    wsplit_kernel<<<dim3(768 / 32, 768 / 32), 256>>>(projw, wproj_h, wproj_l, 768, 768);
    wsplit_kernel<<<dim3(3072 / 32, 768 / 32), 256>>>(w1, w1_h, w1_l, 768, 3072);
    wsplit_kernel<<<dim3(768 / 32, 3072 / 32), 256>>>(w2, w2_h, w2_l, 3072, 768);

    ln1_kernel<<<TOKW, 256>>>(x, ln1w, ln1b);
    tgemm_kernel<0><<<dim3(2304 / 128, TOKW_PAD / 128), 256, SMEM_TG>>>(qkvb, nullptr, nullptr);
    attn_kernel<<<BH, 128, SM_ATT_TOTAL>>>(relh, relw, qidx, kidx);
    tgemm_kernel<1><<<dim3(768 / 128, TOKW_PAD / 128), 256, SMEM_TG>>>(projb, x, nullptr);
    ln2_kernel<<<TOKX, 256>>>(ln2w, ln2b);
    tgemm_kernel<2><<<dim3(3072 / 128, TOKX / 128), 256, SMEM_TG>>>(b1, nullptr, nullptr);
    tgemm_kernel<3><<<dim3(768 / 128, TOKX / 128), 256, SMEM_TG>>>(b2, nullptr, out);
}